// round 2
// baseline (speedup 1.0000x reference)
#include <cuda_runtime.h>
#include <math.h>

namespace {

constexpr int kB    = 4;      // basis kernels
constexpr int kH    = 8;      // heads
constexpr int kNI   = 16384;  // BATCH * N
constexpr int kBlk  = 128;

__device__ int g_dt_default = 1;

__device__ __forceinline__ unsigned long long pack2(float lo, float hi) {
    unsigned long long r;
    asm("mov.b64 %0, {%1, %2};" : "=l"(r) : "f"(lo), "f"(hi));
    return r;
}
__device__ __forceinline__ void unpack2(unsigned long long v, float& lo, float& hi) {
    asm("mov.b64 {%0, %1}, %2;" : "=f"(lo), "=f"(hi) : "l"(v));
}
__device__ __forceinline__ unsigned long long fma2(unsigned long long a,
                                                   unsigned long long b,
                                                   unsigned long long c) {
    unsigned long long r;
    asm("fma.rn.f32x2 %0, %1, %2, %3;" : "=l"(r) : "l"(a), "l"(b), "l"(c));
    return r;
}
__device__ __forceinline__ unsigned long long mul2(unsigned long long a,
                                                   unsigned long long b) {
    unsigned long long r;
    asm("mul.rn.f32x2 %0, %1, %2;" : "=l"(r) : "l"(a), "l"(b));
    return r;
}

// dt arrives as a scalar; reference passes python int 1. Handle either an
// int32 or a float32 payload robustly (deterministic for fixed input).
__device__ __forceinline__ float resolve_dt(const int* dt_raw) {
    int v = __ldg(dt_raw);
    float f = __int_as_float(v);
    float af = fabsf(f);
    if (af >= 1e-6f && af <= 1e6f) return f;   // bits look like a sane float
    return (float)v;                            // else it was an integer
}

// ---------------------------------------------------------------------------
// Fast kernel: fixed shapes (B=4, H=8, NI=16384).
// One thread per (head, column): grid = (NI/128, H), block = 128.
// 131072 threads / 4096 warps -> ~28 warps/SM, single wave of 1024 CTAs.
// The basis-state update is head-independent; replicating it per head costs
// only 2 extra f32x2 FMAs/t and buys 8x the latency-hiding parallelism.
// ---------------------------------------------------------------------------
__global__ void __launch_bounds__(kBlk)
tb_fast(const float* __restrict__ z0, const float* __restrict__ spikes,
        const float* __restrict__ taus, const float* __restrict__ coeffs,
        const int* __restrict__ dt_raw, float* __restrict__ out, int T)
{
    const int idx = blockIdx.x * kBlk + threadIdx.x;
    const int h   = blockIdx.y;

    const float dt = resolve_dt(dt_raw);

    float d[kB];
#pragma unroll
    for (int k = 0; k < kB; ++k)
        d[k] = (float)exp(-(double)dt / (double)__ldg(&taus[k]));

    const unsigned long long d01 = pack2(d[0], d[1]);
    const unsigned long long d23 = pack2(d[2], d[3]);
    const unsigned long long c01 = pack2(__ldg(&coeffs[h * kB + 0]),
                                         __ldg(&coeffs[h * kB + 1]));
    const unsigned long long c23 = pack2(__ldg(&coeffs[h * kB + 2]),
                                         __ldg(&coeffs[h * kB + 3]));

    // Initial state for this (head, column): z0 layout [H, NI, B], 16B aligned.
    const float4 zi = *reinterpret_cast<const float4*>(
        z0 + ((size_t)h * kNI + idx) * kB);
    unsigned long long z01 = pack2(zi.x, zi.y);
    unsigned long long z23 = pack2(zi.z, zi.w);

    const float* sp = spikes + idx;
    float* op = out + (size_t)h * kNI + idx;
    const long long OSTEP = (long long)kH * kNI;

    constexpr int PF = 8;
    float sA[PF];
#pragma unroll
    for (int j = 0; j < PF; ++j) sA[j] = __ldg(sp + (size_t)j * kNI);
    sp += (size_t)PF * kNI;

    for (int t0 = 0; t0 < T; t0 += PF) {
        float sB[PF];
        if (t0 + PF < T) {
#pragma unroll
            for (int j = 0; j < PF; ++j) sB[j] = __ldg(sp + (size_t)j * kNI);
        } else {
#pragma unroll
            for (int j = 0; j < PF; ++j) sB[j] = 0.0f;
        }
        sp += (size_t)PF * kNI;

#pragma unroll
        for (int j = 0; j < PF; ++j) {
            const unsigned long long ss = pack2(sA[j], sA[j]);
            z01 = fma2(d01, z01, ss);
            z23 = fma2(d23, z23, ss);
            unsigned long long p = fma2(c23, z23, mul2(c01, z01));
            float lo, hi;
            unpack2(p, lo, hi);
            __stcs(op, lo + hi);
            op += OSTEP;
        }
#pragma unroll
        for (int j = 0; j < PF; ++j) sA[j] = sB[j];
    }
}

// ---------------------------------------------------------------------------
// Generic fallback (any shapes, Bn <= 16): one thread per (head, idx).
// ---------------------------------------------------------------------------
__global__ void tb_generic(const float* __restrict__ z0,
                           const float* __restrict__ spikes,
                           const float* __restrict__ taus,
                           const float* __restrict__ coeffs,
                           const int* __restrict__ dt_raw,
                           float* __restrict__ out,
                           int T, int NI, int Hn, int Bn)
{
    const int gid = blockIdx.x * blockDim.x + threadIdx.x;
    if (gid >= NI * Hn) return;
    const int idx = gid % NI;
    const int h   = gid / NI;

    const float dt = resolve_dt(dt_raw);

    constexpr int BMAX = 16;
    float z[BMAX], dk[BMAX], ck[BMAX];
    const int Bc = Bn < BMAX ? Bn : BMAX;
    for (int k = 0; k < Bc; ++k) {
        dk[k] = (float)exp(-(double)dt / (double)taus[k]);
        ck[k] = coeffs[h * Bn + k];
        z[k]  = z0[((size_t)h * NI + idx) * Bn + k];
    }
    const float* sp = spikes + idx;
    float* op = out + (size_t)h * NI + idx;
    for (int t = 0; t < T; ++t) {
        const float s = sp[(size_t)t * NI];
        float r = 0.0f;
        for (int k = 0; k < Bc; ++k) {
            z[k] = fmaf(dk[k], z[k], s);
            r = fmaf(ck[k], z[k], r);
        }
        op[(size_t)t * Hn * NI] = r;
    }
}

}  // namespace

extern "C" void kernel_launch(void* const* d_in, const int* in_sizes, int n_in,
                              void* d_out, int out_size)
{
    const float* z0     = (const float*)d_in[0];
    const float* spikes = (const float*)d_in[1];
    const float* taus   = (const float*)d_in[2];
    const float* coeffs = (const float*)d_in[3];

    const int* dt_ptr;
    if (n_in >= 5) {
        dt_ptr = (const int*)d_in[4];
    } else {
        static int* p = nullptr;
        if (!p) cudaGetSymbolAddress((void**)&p, g_dt_default);
        dt_ptr = p;
    }

    float* out = (float*)d_out;

    const int Bn = in_sizes[2];
    const int Hn = in_sizes[3] / Bn;
    const int NI = in_sizes[0] / (Hn * Bn);
    const int T  = in_sizes[1] / NI;

    if (Bn == kB && Hn == kH && NI == kNI && (T % 8) == 0) {
        dim3 grid(kNI / kBlk, kH);
        tb_fast<<<grid, kBlk>>>(z0, spikes, taus, coeffs, dt_ptr, out, T);
    } else {
        const int threads = NI * Hn;
        tb_generic<<<(threads + 127) / 128, 128>>>(
            z0, spikes, taus, coeffs, dt_ptr, out, T, NI, Hn, Bn);
    }
}

// round 3
// speedup vs baseline: 1.0851x; 1.0851x over previous
#include <cuda_runtime.h>
#include <math.h>

namespace {

constexpr int kB    = 4;      // basis kernels
constexpr int kH    = 8;      // heads
constexpr int kNI   = 16384;  // BATCH * N
constexpr int kCPT  = 4;      // columns per thread (float4 IO)
constexpr int kBlk  = 64;     // -> grid = (16384/(4*64)=64, 8) = 512 CTAs

__device__ int g_dt_default = 1;

__device__ __forceinline__ unsigned long long pack2(float lo, float hi) {
    unsigned long long r;
    asm("mov.b64 %0, {%1, %2};" : "=l"(r) : "f"(lo), "f"(hi));
    return r;
}
__device__ __forceinline__ void unpack2(unsigned long long v, float& lo, float& hi) {
    asm("mov.b64 {%0, %1}, %2;" : "=f"(lo), "=f"(hi) : "l"(v));
}
__device__ __forceinline__ unsigned long long fma2(unsigned long long a,
                                                   unsigned long long b,
                                                   unsigned long long c) {
    unsigned long long r;
    asm("fma.rn.f32x2 %0, %1, %2, %3;" : "=l"(r) : "l"(a), "l"(b), "l"(c));
    return r;
}
__device__ __forceinline__ unsigned long long mul2(unsigned long long a,
                                                   unsigned long long b) {
    unsigned long long r;
    asm("mul.rn.f32x2 %0, %1, %2;" : "=l"(r) : "l"(a), "l"(b));
    return r;
}

// dt arrives as a scalar; reference passes python int 1. Handle either an
// int32 or a float32 payload robustly (deterministic for fixed input).
__device__ __forceinline__ float resolve_dt(const int* dt_raw) {
    int v = __ldg(dt_raw);
    float f = __int_as_float(v);
    float af = fabsf(f);
    if (af >= 1e-6f && af <= 1e6f) return f;
    return (float)v;
}

// ---------------------------------------------------------------------------
// Fast kernel: fixed shapes (B=4, H=8, NI=16384).
// Each thread owns 4 consecutive columns of one head:
//   1 x LDG.128 (spikes) + 1 x STG.128 (responses) per thread-timestep,
// cutting warp-level LSU ops 4x vs the STG.32 version (store-issue bound).
// grid = (NI/(4*64), H) = (64, 8) = 512 CTAs of 64 threads.
// ---------------------------------------------------------------------------
__global__ void __launch_bounds__(kBlk)
tb_fast(const float* __restrict__ z0, const float* __restrict__ spikes,
        const float* __restrict__ taus, const float* __restrict__ coeffs,
        const int* __restrict__ dt_raw, float* __restrict__ out, int T)
{
    const int col0 = (blockIdx.x * kBlk + threadIdx.x) * kCPT;
    const int h    = blockIdx.y;

    const float dt = resolve_dt(dt_raw);

    float d[kB];
#pragma unroll
    for (int k = 0; k < kB; ++k)
        d[k] = (float)exp(-(double)dt / (double)__ldg(&taus[k]));

    const unsigned long long d01 = pack2(d[0], d[1]);
    const unsigned long long d23 = pack2(d[2], d[3]);
    const unsigned long long c01 = pack2(__ldg(&coeffs[h * kB + 0]),
                                         __ldg(&coeffs[h * kB + 1]));
    const unsigned long long c23 = pack2(__ldg(&coeffs[h * kB + 2]),
                                         __ldg(&coeffs[h * kB + 3]));

    // Per-column basis states (z0 layout [H, NI, B], 16B aligned rows).
    unsigned long long z01[kCPT], z23[kCPT];
#pragma unroll
    for (int c = 0; c < kCPT; ++c) {
        const float4 zi = *reinterpret_cast<const float4*>(
            z0 + ((size_t)h * kNI + (col0 + c)) * kB);
        z01[c] = pack2(zi.x, zi.y);
        z23[c] = pack2(zi.z, zi.w);
    }

    const float4* sp = reinterpret_cast<const float4*>(spikes + col0);
    float4* op = reinterpret_cast<float4*>(out + (size_t)h * kNI + col0);
    constexpr int SSTEP = kNI / 4;            // float4 stride per timestep
    constexpr long long OSTEP = (long long)kH * kNI / 4;
    const float4 zero4 = make_float4(0.f, 0.f, 0.f, 0.f);

    // Rolling 8-deep spike prefetch.
    constexpr int PF = 8;
    float4 s[PF];
#pragma unroll
    for (int j = 0; j < PF; ++j) s[j] = __ldg(sp + (size_t)j * SSTEP);
    const float4* spn = sp + (size_t)PF * SSTEP;

    for (int t0 = 0; t0 < T; t0 += PF) {
        const bool more = (t0 + PF < T);
#pragma unroll
        for (int j = 0; j < PF; ++j) {
            const float4 sv = s[j];
            s[j] = more ? __ldg(spn) : zero4;
            spn += SSTEP;

            float r[kCPT];
            const float sc[kCPT] = {sv.x, sv.y, sv.z, sv.w};
#pragma unroll
            for (int c = 0; c < kCPT; ++c) {
                const unsigned long long ss = pack2(sc[c], sc[c]);
                z01[c] = fma2(d01, z01[c], ss);
                z23[c] = fma2(d23, z23[c], ss);
                const unsigned long long p =
                    fma2(c23, z23[c], mul2(c01, z01[c]));
                float lo, hi;
                unpack2(p, lo, hi);
                r[c] = lo + hi;
            }
            __stcs(op, make_float4(r[0], r[1], r[2], r[3]));
            op += OSTEP;
        }
    }
}

// ---------------------------------------------------------------------------
// Generic fallback (any shapes, Bn <= 16): one thread per (head, idx).
// ---------------------------------------------------------------------------
__global__ void tb_generic(const float* __restrict__ z0,
                           const float* __restrict__ spikes,
                           const float* __restrict__ taus,
                           const float* __restrict__ coeffs,
                           const int* __restrict__ dt_raw,
                           float* __restrict__ out,
                           int T, int NI, int Hn, int Bn)
{
    const int gid = blockIdx.x * blockDim.x + threadIdx.x;
    if (gid >= NI * Hn) return;
    const int idx = gid % NI;
    const int h   = gid / NI;

    const float dt = resolve_dt(dt_raw);

    constexpr int BMAX = 16;
    float z[BMAX], dk[BMAX], ck[BMAX];
    const int Bc = Bn < BMAX ? Bn : BMAX;
    for (int k = 0; k < Bc; ++k) {
        dk[k] = (float)exp(-(double)dt / (double)taus[k]);
        ck[k] = coeffs[h * Bn + k];
        z[k]  = z0[((size_t)h * NI + idx) * Bn + k];
    }
    const float* sp = spikes + idx;
    float* op = out + (size_t)h * NI + idx;
    for (int t = 0; t < T; ++t) {
        const float s = sp[(size_t)t * NI];
        float r = 0.0f;
        for (int k = 0; k < Bc; ++k) {
            z[k] = fmaf(dk[k], z[k], s);
            r = fmaf(ck[k], z[k], r);
        }
        op[(size_t)t * Hn * NI] = r;
    }
}

}  // namespace

extern "C" void kernel_launch(void* const* d_in, const int* in_sizes, int n_in,
                              void* d_out, int out_size)
{
    const float* z0     = (const float*)d_in[0];
    const float* spikes = (const float*)d_in[1];
    const float* taus   = (const float*)d_in[2];
    const float* coeffs = (const float*)d_in[3];

    const int* dt_ptr;
    if (n_in >= 5) {
        dt_ptr = (const int*)d_in[4];
    } else {
        static int* p = nullptr;
        if (!p) cudaGetSymbolAddress((void**)&p, g_dt_default);
        dt_ptr = p;
    }

    float* out = (float*)d_out;

    const int Bn = in_sizes[2];
    const int Hn = in_sizes[3] / Bn;
    const int NI = in_sizes[0] / (Hn * Bn);
    const int T  = in_sizes[1] / NI;

    if (Bn == kB && Hn == kH && NI == kNI && (T % 8) == 0) {
        dim3 grid(kNI / (kCPT * kBlk), kH);
        tb_fast<<<grid, kBlk>>>(z0, spikes, taus, coeffs, dt_ptr, out, T);
    } else {
        const int threads = NI * Hn;
        tb_generic<<<(threads + 127) / 128, 128>>>(
            z0, spikes, taus, coeffs, dt_ptr, out, T, NI, Hn, Bn);
    }
}

// round 4
// speedup vs baseline: 1.0906x; 1.0051x over previous
#include <cuda_runtime.h>
#include <math.h>

namespace {

constexpr int kB    = 4;      // basis kernels
constexpr int kH    = 8;      // heads
constexpr int kNI   = 16384;  // BATCH * N
constexpr int kCPT  = 4;      // columns per thread (float4 IO)
constexpr int kBlk  = 128;    // 2 heads x 64 col-threads per CTA

__device__ int g_dt_default = 1;

__device__ __forceinline__ unsigned long long pack2(float lo, float hi) {
    unsigned long long r;
    asm("mov.b64 %0, {%1, %2};" : "=l"(r) : "f"(lo), "f"(hi));
    return r;
}
__device__ __forceinline__ void unpack2(unsigned long long v, float& lo, float& hi) {
    asm("mov.b64 {%0, %1}, %2;" : "=f"(lo), "=f"(hi) : "l"(v));
}
__device__ __forceinline__ unsigned long long fma2(unsigned long long a,
                                                   unsigned long long b,
                                                   unsigned long long c) {
    unsigned long long r;
    asm("fma.rn.f32x2 %0, %1, %2, %3;" : "=l"(r) : "l"(a), "l"(b), "l"(c));
    return r;
}
__device__ __forceinline__ unsigned long long mul2(unsigned long long a,
                                                   unsigned long long b) {
    unsigned long long r;
    asm("mul.rn.f32x2 %0, %1, %2;" : "=l"(r) : "l"(a), "l"(b));
    return r;
}

// dt arrives as a scalar; reference passes python int 1. Handle either an
// int32 or a float32 payload robustly (deterministic for fixed input).
__device__ __forceinline__ float resolve_dt(const int* dt_raw) {
    int v = __ldg(dt_raw);
    float f = __int_as_float(v);
    float af = fabsf(f);
    if (af >= 1e-6f && af <= 1e6f) return f;
    return (float)v;
}

// ---------------------------------------------------------------------------
// Fast kernel: fixed shapes (B=4, H=8, NI=16384).
// Each thread owns 4 consecutive columns of one head:
//   1 x LDG.128 (spikes) + 1 x STG.128 (responses, DEFAULT write-back policy)
// per thread-timestep. CTA = 128 threads = 2 heads x 64 column-threads.
// grid = (NI/(4*64), H/2) = (64, 4) = 512 CTAs -> 3.46 CTA/SM, 13.8 warps/SM.
// Experiment vs R3: __stcs -> default stores (test .cs-writeback-throttle
// hypothesis), plus 2x per-SM in-flight store depth.
// ---------------------------------------------------------------------------
__global__ void __launch_bounds__(kBlk)
tb_fast(const float* __restrict__ z0, const float* __restrict__ spikes,
        const float* __restrict__ taus, const float* __restrict__ coeffs,
        const int* __restrict__ dt_raw, float* __restrict__ out, int T)
{
    const int lane = threadIdx.x & 63;
    const int h    = blockIdx.y * 2 + (threadIdx.x >> 6);
    const int col0 = (blockIdx.x * 64 + lane) * kCPT;

    const float dt = resolve_dt(dt_raw);

    float d[kB];
#pragma unroll
    for (int k = 0; k < kB; ++k)
        d[k] = (float)exp(-(double)dt / (double)__ldg(&taus[k]));

    const unsigned long long d01 = pack2(d[0], d[1]);
    const unsigned long long d23 = pack2(d[2], d[3]);
    const unsigned long long c01 = pack2(__ldg(&coeffs[h * kB + 0]),
                                         __ldg(&coeffs[h * kB + 1]));
    const unsigned long long c23 = pack2(__ldg(&coeffs[h * kB + 2]),
                                         __ldg(&coeffs[h * kB + 3]));

    // Per-column basis states (z0 layout [H, NI, B], 16B aligned rows).
    unsigned long long z01[kCPT], z23[kCPT];
#pragma unroll
    for (int c = 0; c < kCPT; ++c) {
        const float4 zi = *reinterpret_cast<const float4*>(
            z0 + ((size_t)h * kNI + (col0 + c)) * kB);
        z01[c] = pack2(zi.x, zi.y);
        z23[c] = pack2(zi.z, zi.w);
    }

    const float4* sp = reinterpret_cast<const float4*>(spikes + col0);
    float4* op = reinterpret_cast<float4*>(out + (size_t)h * kNI + col0);
    constexpr int SSTEP = kNI / 4;            // float4 stride per timestep
    constexpr long long OSTEP = (long long)kH * kNI / 4;
    const float4 zero4 = make_float4(0.f, 0.f, 0.f, 0.f);

    // Rolling 8-deep spike prefetch.
    constexpr int PF = 8;
    float4 s[PF];
#pragma unroll
    for (int j = 0; j < PF; ++j) s[j] = __ldg(sp + (size_t)j * SSTEP);
    const float4* spn = sp + (size_t)PF * SSTEP;

    for (int t0 = 0; t0 < T; t0 += PF) {
        const bool more = (t0 + PF < T);
#pragma unroll
        for (int j = 0; j < PF; ++j) {
            const float4 sv = s[j];
            s[j] = more ? __ldg(spn) : zero4;
            spn += SSTEP;

            float r[kCPT];
            const float sc[kCPT] = {sv.x, sv.y, sv.z, sv.w};
#pragma unroll
            for (int c = 0; c < kCPT; ++c) {
                const unsigned long long ss = pack2(sc[c], sc[c]);
                z01[c] = fma2(d01, z01[c], ss);
                z23[c] = fma2(d23, z23[c], ss);
                const unsigned long long p =
                    fma2(c23, z23[c], mul2(c01, z01[c]));
                float lo, hi;
                unpack2(p, lo, hi);
                r[c] = lo + hi;
            }
            *op = make_float4(r[0], r[1], r[2], r[3]);   // default write-back STG.128
            op += OSTEP;
        }
    }
}

// ---------------------------------------------------------------------------
// Generic fallback (any shapes, Bn <= 16): one thread per (head, idx).
// ---------------------------------------------------------------------------
__global__ void tb_generic(const float* __restrict__ z0,
                           const float* __restrict__ spikes,
                           const float* __restrict__ taus,
                           const float* __restrict__ coeffs,
                           const int* __restrict__ dt_raw,
                           float* __restrict__ out,
                           int T, int NI, int Hn, int Bn)
{
    const int gid = blockIdx.x * blockDim.x + threadIdx.x;
    if (gid >= NI * Hn) return;
    const int idx = gid % NI;
    const int h   = gid / NI;

    const float dt = resolve_dt(dt_raw);

    constexpr int BMAX = 16;
    float z[BMAX], dk[BMAX], ck[BMAX];
    const int Bc = Bn < BMAX ? Bn : BMAX;
    for (int k = 0; k < Bc; ++k) {
        dk[k] = (float)exp(-(double)dt / (double)taus[k]);
        ck[k] = coeffs[h * Bn + k];
        z[k]  = z0[((size_t)h * NI + idx) * Bn + k];
    }
    const float* sp = spikes + idx;
    float* op = out + (size_t)h * NI + idx;
    for (int t = 0; t < T; ++t) {
        const float s = sp[(size_t)t * NI];
        float r = 0.0f;
        for (int k = 0; k < Bc; ++k) {
            z[k] = fmaf(dk[k], z[k], s);
            r = fmaf(ck[k], z[k], r);
        }
        op[(size_t)t * Hn * NI] = r;
    }
}

}  // namespace

extern "C" void kernel_launch(void* const* d_in, const int* in_sizes, int n_in,
                              void* d_out, int out_size)
{
    const float* z0     = (const float*)d_in[0];
    const float* spikes = (const float*)d_in[1];
    const float* taus   = (const float*)d_in[2];
    const float* coeffs = (const float*)d_in[3];

    const int* dt_ptr;
    if (n_in >= 5) {
        dt_ptr = (const int*)d_in[4];
    } else {
        static int* p = nullptr;
        if (!p) cudaGetSymbolAddress((void**)&p, g_dt_default);
        dt_ptr = p;
    }

    float* out = (float*)d_out;

    const int Bn = in_sizes[2];
    const int Hn = in_sizes[3] / Bn;
    const int NI = in_sizes[0] / (Hn * Bn);
    const int T  = in_sizes[1] / NI;

    if (Bn == kB && Hn == kH && NI == kNI && (T % 8) == 0) {
        dim3 grid(kNI / (kCPT * 64), kH / 2);
        tb_fast<<<grid, kBlk>>>(z0, spikes, taus, coeffs, dt_ptr, out, T);
    } else {
        const int threads = NI * Hn;
        tb_generic<<<(threads + 127) / 128, 128>>>(
            z0, spikes, taus, coeffs, dt_ptr, out, T, NI, Hn, Bn);
    }
}

// round 5
// speedup vs baseline: 1.1982x; 1.0987x over previous
#include <cuda_runtime.h>
#include <math.h>

namespace {

constexpr int kB    = 4;      // basis kernels
constexpr int kH    = 8;      // heads
constexpr int kNI   = 16384;  // BATCH * N
constexpr int kBlk  = 128;    // threads per CTA
constexpr int kCPT  = 2;      // columns per thread
constexpr int kCols = kBlk * kCPT;        // 256 columns per CTA
constexpr int kTT   = 8;      // timesteps buffered per chunk
constexpr int kNBuf = 4;      // SMEM buffers (3 outstanding bulk groups)
constexpr int kRowBytes = kCols * 4;      // 1024 B contiguous per (t,h) row

__device__ int g_dt_default = 1;

__device__ __forceinline__ unsigned long long pack2(float lo, float hi) {
    unsigned long long r;
    asm("mov.b64 %0, {%1, %2};" : "=l"(r) : "f"(lo), "f"(hi));
    return r;
}
__device__ __forceinline__ void unpack2(unsigned long long v, float& lo, float& hi) {
    asm("mov.b64 {%0, %1}, %2;" : "=f"(lo), "=f"(hi) : "l"(v));
}
__device__ __forceinline__ unsigned long long fma2(unsigned long long a,
                                                   unsigned long long b,
                                                   unsigned long long c) {
    unsigned long long r;
    asm("fma.rn.f32x2 %0, %1, %2, %3;" : "=l"(r) : "l"(a), "l"(b), "l"(c));
    return r;
}
__device__ __forceinline__ unsigned long long mul2(unsigned long long a,
                                                   unsigned long long b) {
    unsigned long long r;
    asm("mul.rn.f32x2 %0, %1, %2;" : "=l"(r) : "l"(a), "l"(b));
    return r;
}

__device__ __forceinline__ unsigned smem_u32(const void* p) {
    unsigned r;
    asm("{ .reg .u64 t; cvta.to.shared.u64 t, %1; cvt.u32.u64 %0, t; }"
        : "=r"(r) : "l"(p));
    return r;
}

// dt arrives as a scalar; reference passes python int 1. Handle either an
// int32 or a float32 payload robustly (deterministic for fixed input).
__device__ __forceinline__ float resolve_dt(const int* dt_raw) {
    int v = __ldg(dt_raw);
    float f = __int_as_float(v);
    float af = fabsf(f);
    if (af >= 1e-6f && af <= 1e6f) return f;
    return (float)v;
}

// ---------------------------------------------------------------------------
// Fast kernel (B=4, H=8, NI=16384): outputs staged in SMEM and written via
// cp.async.bulk (TMA/async-proxy) instead of per-thread STG — tests whether
// the ~3 TB/s plateau is an LSU store-queue depth cap (per-SM Little's law).
// CTA = 128 threads x 2 cols = 256 consecutive columns of one head.
// grid = (16384/256, 8) = (64, 8) = 512 CTAs.
// Per chunk of 8 timesteps: compute -> STS (1KB row per t) -> 8 bulk stores,
// 4 SMEM buffers so 3 bulk groups (24 KB) stay in flight per CTA.
// ---------------------------------------------------------------------------
__global__ void __launch_bounds__(kBlk)
tb_fast(const float* __restrict__ z0, const float* __restrict__ spikes,
        const float* __restrict__ taus, const float* __restrict__ coeffs,
        const int* __restrict__ dt_raw, float* __restrict__ out, int T)
{
    __shared__ __align__(16) float sbuf[kNBuf][kTT][kCols];

    const int h    = blockIdx.y;
    const int col0 = blockIdx.x * kCols + threadIdx.x * kCPT;

    const float dt = resolve_dt(dt_raw);

    float d[kB];
#pragma unroll
    for (int k = 0; k < kB; ++k)
        d[k] = (float)exp(-(double)dt / (double)__ldg(&taus[k]));

    const unsigned long long d01 = pack2(d[0], d[1]);
    const unsigned long long d23 = pack2(d[2], d[3]);
    const unsigned long long c01 = pack2(__ldg(&coeffs[h * kB + 0]),
                                         __ldg(&coeffs[h * kB + 1]));
    const unsigned long long c23 = pack2(__ldg(&coeffs[h * kB + 2]),
                                         __ldg(&coeffs[h * kB + 3]));

    // Per-column basis states (z0 layout [H, NI, B], 16B-aligned rows).
    unsigned long long z01[kCPT], z23[kCPT];
#pragma unroll
    for (int c = 0; c < kCPT; ++c) {
        const float4 zi = *reinterpret_cast<const float4*>(
            z0 + ((size_t)h * kNI + (col0 + c)) * kB);
        z01[c] = pack2(zi.x, zi.y);
        z23[c] = pack2(zi.z, zi.w);
    }

    const float2* sp = reinterpret_cast<const float2*>(spikes + col0);
    constexpr int SSTEP = kNI / 2;                 // float2 stride per timestep
    const float2 zero2 = make_float2(0.f, 0.f);

    // Output row base for this CTA: out[t, h, blockIdx.x*kCols ...]
    const float* orow = out + (size_t)h * kNI + (size_t)blockIdx.x * kCols;
    constexpr long long OSTEP = (long long)kH * kNI;   // floats per timestep

    // Rolling 8-deep spike prefetch.
    float2 s[kTT];
#pragma unroll
    for (int j = 0; j < kTT; ++j) s[j] = __ldg(sp + (size_t)j * SSTEP);
    const float2* spn = sp + (size_t)kTT * SSTEP;

    const int nChunks = T / kTT;
    for (int c = 0; c < nChunks; ++c) {
        const int buf = c & (kNBuf - 1);

        // Ensure this buffer's previous bulk group has read SMEM.
        if (threadIdx.x == 0)
            asm volatile("cp.async.bulk.wait_group.read %0;" :: "n"(kNBuf - 1)
                         : "memory");
        __syncthreads();

        const bool more = ((c + 1) * kTT < T);
#pragma unroll
        for (int j = 0; j < kTT; ++j) {
            const float2 sv = s[j];
            s[j] = more ? __ldg(spn) : zero2;
            spn += SSTEP;

            float r[kCPT];
            const float sc[kCPT] = {sv.x, sv.y};
#pragma unroll
            for (int cc = 0; cc < kCPT; ++cc) {
                const unsigned long long ss = pack2(sc[cc], sc[cc]);
                z01[cc] = fma2(d01, z01[cc], ss);
                z23[cc] = fma2(d23, z23[cc], ss);
                const unsigned long long p =
                    fma2(c23, z23[cc], mul2(c01, z01[cc]));
                float lo, hi;
                unpack2(p, lo, hi);
                r[cc] = lo + hi;
            }
            reinterpret_cast<float2*>(sbuf[buf][j])[threadIdx.x] =
                make_float2(r[0], r[1]);
        }

        // Make generic-proxy SMEM writes visible to the async proxy.
        asm volatile("fence.proxy.async.shared::cta;" ::: "memory");
        __syncthreads();

        if (threadIdx.x == 0) {
            const float* og = orow + (size_t)c * kTT * OSTEP;
#pragma unroll
            for (int j = 0; j < kTT; ++j) {
                asm volatile(
                    "cp.async.bulk.global.shared::cta.bulk_group [%0], [%1], %2;"
                    :: "l"(og + (size_t)j * OSTEP),
                       "r"(smem_u32(&sbuf[buf][j][0])),
                       "r"(kRowBytes)
                    : "memory");
            }
            asm volatile("cp.async.bulk.commit_group;" ::: "memory");
        }
    }

    // Drain all outstanding bulk stores before exit.
    if (threadIdx.x == 0)
        asm volatile("cp.async.bulk.wait_group %0;" :: "n"(0) : "memory");
}

// ---------------------------------------------------------------------------
// Generic fallback (any shapes, Bn <= 16): one thread per (head, idx).
// ---------------------------------------------------------------------------
__global__ void tb_generic(const float* __restrict__ z0,
                           const float* __restrict__ spikes,
                           const float* __restrict__ taus,
                           const float* __restrict__ coeffs,
                           const int* __restrict__ dt_raw,
                           float* __restrict__ out,
                           int T, int NI, int Hn, int Bn)
{
    const int gid = blockIdx.x * blockDim.x + threadIdx.x;
    if (gid >= NI * Hn) return;
    const int idx = gid % NI;
    const int h   = gid / NI;

    const float dt = resolve_dt(dt_raw);

    constexpr int BMAX = 16;
    float z[BMAX], dk[BMAX], ck[BMAX];
    const int Bc = Bn < BMAX ? Bn : BMAX;
    for (int k = 0; k < Bc; ++k) {
        dk[k] = (float)exp(-(double)dt / (double)taus[k]);
        ck[k] = coeffs[h * Bn + k];
        z[k]  = z0[((size_t)h * NI + idx) * Bn + k];
    }
    const float* sp = spikes + idx;
    float* op = out + (size_t)h * NI + idx;
    for (int t = 0; t < T; ++t) {
        const float s = sp[(size_t)t * NI];
        float r = 0.0f;
        for (int k = 0; k < Bc; ++k) {
            z[k] = fmaf(dk[k], z[k], s);
            r = fmaf(ck[k], z[k], r);
        }
        op[(size_t)t * Hn * NI] = r;
    }
}

}  // namespace

extern "C" void kernel_launch(void* const* d_in, const int* in_sizes, int n_in,
                              void* d_out, int out_size)
{
    const float* z0     = (const float*)d_in[0];
    const float* spikes = (const float*)d_in[1];
    const float* taus   = (const float*)d_in[2];
    const float* coeffs = (const float*)d_in[3];

    const int* dt_ptr;
    if (n_in >= 5) {
        dt_ptr = (const int*)d_in[4];
    } else {
        static int* p = nullptr;
        if (!p) cudaGetSymbolAddress((void**)&p, g_dt_default);
        dt_ptr = p;
    }

    float* out = (float*)d_out;

    const int Bn = in_sizes[2];
    const int Hn = in_sizes[3] / Bn;
    const int NI = in_sizes[0] / (Hn * Bn);
    const int T  = in_sizes[1] / NI;

    if (Bn == kB && Hn == kH && NI == kNI && (T % kTT) == 0) {
        dim3 grid(kNI / kCols, kH);
        tb_fast<<<grid, kBlk>>>(z0, spikes, taus, coeffs, dt_ptr, out, T);
    } else {
        const int threads = NI * Hn;
        tb_generic<<<(threads + 127) / 128, 128>>>(
            z0, spikes, taus, coeffs, dt_ptr, out, T, NI, Hn, Bn);
    }
}

// round 6
// speedup vs baseline: 1.3059x; 1.0898x over previous
#include <cuda_runtime.h>
#include <math.h>

namespace {

constexpr int kB     = 4;      // basis kernels
constexpr int kH     = 8;      // heads
constexpr int kNI    = 16384;  // BATCH * N
constexpr int kBlk   = 128;    // threads per CTA (1 column each)
constexpr int kHPT   = 2;      // heads per CTA
constexpr int kCols  = 128;    // columns per CTA
constexpr int kTT    = 8;      // timesteps per chunk
constexpr int kNBuf  = 3;      // triple-buffered spike-in / result-out
constexpr int kSpkRowB = kCols * 4;          // 512 B
constexpr int kSpkChunkB = kTT * kSpkRowB;   // 4096 B per chunk
constexpr int kOutRowB = kCols * 4;          // 512 B

__device__ int g_dt_default = 1;

__device__ __forceinline__ unsigned long long pack2(float lo, float hi) {
    unsigned long long r;
    asm("mov.b64 %0, {%1, %2};" : "=l"(r) : "f"(lo), "f"(hi));
    return r;
}
__device__ __forceinline__ void unpack2(unsigned long long v, float& lo, float& hi) {
    asm("mov.b64 {%0, %1}, %2;" : "=f"(lo), "=f"(hi) : "l"(v));
}
__device__ __forceinline__ unsigned long long fma2(unsigned long long a,
                                                   unsigned long long b,
                                                   unsigned long long c) {
    unsigned long long r;
    asm("fma.rn.f32x2 %0, %1, %2, %3;" : "=l"(r) : "l"(a), "l"(b), "l"(c));
    return r;
}
__device__ __forceinline__ unsigned long long mul2(unsigned long long a,
                                                   unsigned long long b) {
    unsigned long long r;
    asm("mul.rn.f32x2 %0, %1, %2;" : "=l"(r) : "l"(a), "l"(b));
    return r;
}

__device__ __forceinline__ unsigned smem_u32(const void* p) {
    unsigned r;
    asm("{ .reg .u64 t; cvta.to.shared.u64 t, %1; cvt.u32.u64 %0, t; }"
        : "=r"(r) : "l"(p));
    return r;
}

__device__ __forceinline__ void mbar_init(unsigned addr, unsigned count) {
    asm volatile("mbarrier.init.shared.b64 [%0], %1;" :: "r"(addr), "r"(count)
                 : "memory");
}
__device__ __forceinline__ void mbar_expect_tx(unsigned addr, unsigned bytes) {
    asm volatile("mbarrier.arrive.expect_tx.shared.b64 _, [%0], %1;"
                 :: "r"(addr), "r"(bytes) : "memory");
}
__device__ __forceinline__ void mbar_wait(unsigned addr, unsigned parity) {
    asm volatile(
        "{\n\t"
        ".reg .pred P1;\n\t"
        "WAIT_LOOP_%=:\n\t"
        "mbarrier.try_wait.parity.shared::cta.b64 P1, [%0], %1;\n\t"
        "@P1 bra.uni WAIT_DONE_%=;\n\t"
        "bra.uni WAIT_LOOP_%=;\n\t"
        "WAIT_DONE_%=:\n\t"
        "}"
        :: "r"(addr), "r"(parity) : "memory");
}

__device__ __forceinline__ void bulk_g2s(unsigned dst_smem, const void* src,
                                         unsigned bytes, unsigned mbar) {
    asm volatile(
        "cp.async.bulk.shared::cluster.global.mbarrier::complete_tx::bytes "
        "[%0], [%1], %2, [%3];"
        :: "r"(dst_smem), "l"(src), "r"(bytes), "r"(mbar) : "memory");
}
__device__ __forceinline__ void bulk_s2g(const void* dst, unsigned src_smem,
                                         unsigned bytes) {
    asm volatile(
        "cp.async.bulk.global.shared::cta.bulk_group [%0], [%1], %2;"
        :: "l"(dst), "r"(src_smem), "r"(bytes) : "memory");
}

// dt arrives as a scalar; reference passes python int 1. Handle either an
// int32 or a float32 payload robustly (deterministic for fixed input).
__device__ __forceinline__ float resolve_dt(const int* dt_raw) {
    int v = __ldg(dt_raw);
    float f = __int_as_float(v);
    float af = fabsf(f);
    if (af >= 1e-6f && af <= 1e6f) return f;
    return (float)v;
}

// ---------------------------------------------------------------------------
// Fast kernel (B=4, H=8, NI=16384). Fully async-proxy IO:
//   spikes: TMA bulk loads into SMEM, 3 chunks (24 timesteps) ahead — the
//           per-thread loop has NO global-load latency in its dependency chain
//   output: staged in SMEM, TMA bulk stores (3 groups in flight)
// CTA = 128 threads = 128 columns x 2 heads. grid = (128, 4) = 512 CTAs.
// ---------------------------------------------------------------------------
__global__ void __launch_bounds__(kBlk)
tb_fast(const float* __restrict__ z0, const float* __restrict__ spikes,
        const float* __restrict__ taus, const float* __restrict__ coeffs,
        const int* __restrict__ dt_raw, float* __restrict__ out, int T)
{
    __shared__ __align__(16) float sspk[kNBuf][kTT][kCols];
    __shared__ __align__(16) float sout[kNBuf][kTT][kHPT][kCols];
    __shared__ __align__(8) unsigned long long mbar[kNBuf];

    const int tid  = threadIdx.x;
    const int h0   = blockIdx.y * kHPT;
    const int col0 = blockIdx.x * kCols;
    const int col  = col0 + tid;

    const float dt = resolve_dt(dt_raw);

    float d[kB];
#pragma unroll
    for (int k = 0; k < kB; ++k)
        d[k] = (float)exp(-(double)dt / (double)__ldg(&taus[k]));

    const unsigned long long d01 = pack2(d[0], d[1]);
    const unsigned long long d23 = pack2(d[2], d[3]);
    unsigned long long c01[kHPT], c23[kHPT], z01[kHPT], z23[kHPT];
#pragma unroll
    for (int hh = 0; hh < kHPT; ++hh) {
        const int h = h0 + hh;
        c01[hh] = pack2(__ldg(&coeffs[h * kB + 0]), __ldg(&coeffs[h * kB + 1]));
        c23[hh] = pack2(__ldg(&coeffs[h * kB + 2]), __ldg(&coeffs[h * kB + 3]));
        const float4 zi = *reinterpret_cast<const float4*>(
            z0 + ((size_t)h * kNI + col) * kB);
        z01[hh] = pack2(zi.x, zi.y);
        z23[hh] = pack2(zi.z, zi.w);
    }

    const int nChunks = T / kTT;

    // mbarrier init + prologue spike loads (3 chunks ahead).
    if (tid == 0) {
#pragma unroll
        for (int b = 0; b < kNBuf; ++b) mbar_init(smem_u32(&mbar[b]), 1);
        asm volatile("fence.proxy.async.shared::cta;" ::: "memory");
#pragma unroll
        for (int b = 0; b < kNBuf; ++b) {
            mbar_expect_tx(smem_u32(&mbar[b]), kSpkChunkB);
#pragma unroll
            for (int j = 0; j < kTT; ++j)
                bulk_g2s(smem_u32(&sspk[b][j][0]),
                         spikes + (size_t)(b * kTT + j) * kNI + col0,
                         kSpkRowB, smem_u32(&mbar[b]));
        }
    }
    __syncthreads();

    for (int c = 0; c < nChunks; ++c) {
        const int buf = c % kNBuf;

        // Output-buffer reuse guard: <=2 bulk store groups outstanding.
        if (tid == 0)
            asm volatile("cp.async.bulk.wait_group.read %0;" :: "n"(kNBuf - 1)
                         : "memory");
        __syncthreads();

        // Wait for this chunk's spike tile.
        mbar_wait(smem_u32(&mbar[buf]), (c / kNBuf) & 1);

#pragma unroll
        for (int j = 0; j < kTT; ++j) {
            const float s = sspk[buf][j][tid];
            const unsigned long long ss = pack2(s, s);
#pragma unroll
            for (int hh = 0; hh < kHPT; ++hh) {
                z01[hh] = fma2(d01, z01[hh], ss);
                z23[hh] = fma2(d23, z23[hh], ss);
                const unsigned long long p =
                    fma2(c23[hh], z23[hh], mul2(c01[hh], z01[hh]));
                float lo, hi;
                unpack2(p, lo, hi);
                sout[buf][j][hh][tid] = lo + hi;
            }
        }

        asm volatile("fence.proxy.async.shared::cta;" ::: "memory");
        __syncthreads();

        if (tid == 0) {
            const int tbase = c * kTT;
#pragma unroll
            for (int j = 0; j < kTT; ++j) {
#pragma unroll
                for (int hh = 0; hh < kHPT; ++hh) {
                    bulk_s2g(out + ((size_t)(tbase + j) * kH + h0 + hh) * kNI
                                 + col0,
                             smem_u32(&sout[buf][j][hh][0]), kOutRowB);
                }
            }
            asm volatile("cp.async.bulk.commit_group;" ::: "memory");

            // Refill this spike buffer for chunk c + kNBuf.
            const int cn = c + kNBuf;
            if (cn < nChunks) {
                mbar_expect_tx(smem_u32(&mbar[buf]), kSpkChunkB);
#pragma unroll
                for (int j = 0; j < kTT; ++j)
                    bulk_g2s(smem_u32(&sspk[buf][j][0]),
                             spikes + (size_t)(cn * kTT + j) * kNI + col0,
                             kSpkRowB, smem_u32(&mbar[buf]));
            }
        }
    }

    if (tid == 0)
        asm volatile("cp.async.bulk.wait_group %0;" :: "n"(0) : "memory");
}

// ---------------------------------------------------------------------------
// Generic fallback (any shapes, Bn <= 16): one thread per (head, idx).
// ---------------------------------------------------------------------------
__global__ void tb_generic(const float* __restrict__ z0,
                           const float* __restrict__ spikes,
                           const float* __restrict__ taus,
                           const float* __restrict__ coeffs,
                           const int* __restrict__ dt_raw,
                           float* __restrict__ out,
                           int T, int NI, int Hn, int Bn)
{
    const int gid = blockIdx.x * blockDim.x + threadIdx.x;
    if (gid >= NI * Hn) return;
    const int idx = gid % NI;
    const int h   = gid / NI;

    const float dt = resolve_dt(dt_raw);

    constexpr int BMAX = 16;
    float z[BMAX], dk[BMAX], ck[BMAX];
    const int Bc = Bn < BMAX ? Bn : BMAX;
    for (int k = 0; k < Bc; ++k) {
        dk[k] = (float)exp(-(double)dt / (double)taus[k]);
        ck[k] = coeffs[h * Bn + k];
        z[k]  = z0[((size_t)h * NI + idx) * Bn + k];
    }
    const float* sp = spikes + idx;
    float* op = out + (size_t)h * NI + idx;
    for (int t = 0; t < T; ++t) {
        const float s = sp[(size_t)t * NI];
        float r = 0.0f;
        for (int k = 0; k < Bc; ++k) {
            z[k] = fmaf(dk[k], z[k], s);
            r = fmaf(ck[k], z[k], r);
        }
        op[(size_t)t * Hn * NI] = r;
    }
}

}  // namespace

extern "C" void kernel_launch(void* const* d_in, const int* in_sizes, int n_in,
                              void* d_out, int out_size)
{
    const float* z0     = (const float*)d_in[0];
    const float* spikes = (const float*)d_in[1];
    const float* taus   = (const float*)d_in[2];
    const float* coeffs = (const float*)d_in[3];

    const int* dt_ptr;
    if (n_in >= 5) {
        dt_ptr = (const int*)d_in[4];
    } else {
        static int* p = nullptr;
        if (!p) cudaGetSymbolAddress((void**)&p, g_dt_default);
        dt_ptr = p;
    }

    float* out = (float*)d_out;

    const int Bn = in_sizes[2];
    const int Hn = in_sizes[3] / Bn;
    const int NI = in_sizes[0] / (Hn * Bn);
    const int T  = in_sizes[1] / NI;

    if (Bn == kB && Hn == kH && NI == kNI && (T % kTT) == 0 &&
        T >= kTT * kNBuf) {
        dim3 grid(kNI / kCols, kH / kHPT);
        tb_fast<<<grid, kBlk>>>(z0, spikes, taus, coeffs, dt_ptr, out, T);
    } else {
        const int threads = NI * Hn;
        tb_generic<<<(threads + 127) / 128, 128>>>(
            z0, spikes, taus, coeffs, dt_ptr, out, T, NI, Hn, Bn);
    }
}